// round 16
// baseline (speedup 1.0000x reference)
#include <cuda_runtime.h>
#include <cuda_fp16.h>
#include <stdint.h>

#define B_ 2
#define T_ 2048
#define C_ 768
#define H_ 12
#define D_ 64
#define WIN_ 256
#define NC3_ (3*C_)
#define QSCALE_ 0.18033688011112042f   // 0.125 * log2(e)

// -------- scratch (allocation-free: __device__ globals) --------
__device__ __align__(16) __half g_xh[B_*T_*C_];
__device__ __align__(16) __half g_wa[3*C_*C_];    // c_attn_w transposed: [n][k]
__device__ __align__(16) __half g_wp[C_*C_];      // c_proj_w transposed: [n][k]
__device__ __align__(16) __half g_qkv[B_*T_*NC3_]; // [b,t,3C]; q part pre-scaled
__device__ __align__(16) __half g_ah[B_*T_*C_];   // attention out, fp16
__device__ float g_gate[B_*T_];

// ============================================================
// helpers
// ============================================================
__device__ __forceinline__ void mma16816(float* d, const uint32_t* a,
                                         uint32_t b0, uint32_t b1) {
    asm volatile(
        "mma.sync.aligned.m16n8k16.row.col.f32.f16.f16.f32 "
        "{%0,%1,%2,%3}, {%4,%5,%6,%7}, {%8,%9}, {%0,%1,%2,%3};"
        : "+f"(d[0]), "+f"(d[1]), "+f"(d[2]), "+f"(d[3])
        : "r"(a[0]), "r"(a[1]), "r"(a[2]), "r"(a[3]), "r"(b0), "r"(b1));
}

__device__ __forceinline__ void ldmx4(uint32_t* r, uint32_t addr) {
    asm volatile("ldmatrix.sync.aligned.m8n8.x4.shared.b16 {%0,%1,%2,%3}, [%4];"
                 : "=r"(r[0]), "=r"(r[1]), "=r"(r[2]), "=r"(r[3]) : "r"(addr));
}
__device__ __forceinline__ void ldmx4t(uint32_t* r, uint32_t addr) {
    asm volatile("ldmatrix.sync.aligned.m8n8.x4.trans.shared.b16 {%0,%1,%2,%3}, [%4];"
                 : "=r"(r[0]), "=r"(r[1]), "=r"(r[2]), "=r"(r[3]) : "r"(addr));
}

__device__ __forceinline__ uint32_t pack2(float a, float b) {
    __half2 h = __floats2half2_rn(a, b);
    return *(uint32_t*)&h;
}

__device__ __forceinline__ float ex2(float x) {
    float y;
    asm("ex2.approx.ftz.f32 %0, %1;" : "=f"(y) : "f"(x));
    return y;
}

__device__ __forceinline__ uint32_t sm_u32(const void* p) {
    return (uint32_t)__cvta_generic_to_shared(p);
}

#define CP_A16(dst, src) \
    asm volatile("cp.async.cg.shared.global [%0], [%1], 16;" :: "r"(dst), "l"(src))
#define CP_COMMIT()  asm volatile("cp.async.commit_group;")
#define CP_WAIT1()   asm volatile("cp.async.wait_group 1;")

// ============================================================
// prep kernels
// ============================================================
#define PREP_X_   3072
#define PREP_WA_  1728
#define PREP_WP_  576
#define PREP_SEL_ 512

__global__ __launch_bounds__(256) void prep_a_kernel(
        const float4* __restrict__ x4,
        const float*  __restrict__ c_attn_w) {
    __shared__ float tile[32][33];
    int bid = blockIdx.x;
    int tid = threadIdx.x;

    if (bid < PREP_X_) {
        int i = bid * 256 + tid;
        float4 f = x4[i];
        uint2 o;
        o.x = pack2(f.x, f.y);
        o.y = pack2(f.z, f.w);
        *(uint2*)&g_xh[(size_t)i * 4] = o;
        return;
    }
    bid -= PREP_X_;
    {   // c_attn_w transpose [C_ x 3C] -> g_wa [3C x C_]
        int bx = bid % 72, by = bid / 72;
        int bn = bx * 32, bk = by * 32;
        int tx = tid & 31, ty = tid >> 5;
        #pragma unroll
        for (int r = 0; r < 4; r++) {
            int k = bk + ty + r * 8;
            tile[ty + r * 8][tx] = c_attn_w[(size_t)k * NC3_ + bn + tx];
        }
        __syncthreads();
        #pragma unroll
        for (int r = 0; r < 4; r++) {
            int n = bn + ty + r * 8;
            g_wa[(size_t)n * C_ + bk + tx] = __float2half(tile[tx][ty + r * 8]);
        }
    }
}

__global__ __launch_bounds__(256) void prep_b_kernel(
        const float*  __restrict__ c_proj_w,
        const float*  __restrict__ mamba,
        const float*  __restrict__ ln_w,
        const float*  __restrict__ ln_b,
        const float*  __restrict__ mscale,
        const float*  __restrict__ sel_w,
        const float*  __restrict__ sel_b) {
    __shared__ float tile[32][33];
    int bid = blockIdx.x;
    int tid = threadIdx.x;

    if (bid < PREP_WP_) {
        int bx = bid % 24, by = bid / 24;
        int bn = bx * 32, bk = by * 32;
        int tx = tid & 31, ty = tid >> 5;
        #pragma unroll
        for (int r = 0; r < 4; r++) {
            int k = bk + ty + r * 8;
            tile[ty + r * 8][tx] = c_proj_w[(size_t)k * C_ + bn + tx];
        }
        __syncthreads();
        #pragma unroll
        for (int r = 0; r < 4; r++) {
            int n = bn + ty + r * 8;
            g_wp[(size_t)n * C_ + bk + tx] = __float2half(tile[tx][ty + r * 8]);
        }
        return;
    }
    bid -= PREP_WP_;
    {
        int row  = bid * 8 + (tid >> 5);
        int lane = tid & 31;
        const float4* xr = (const float4*)(mamba + (size_t)row * C_);
        const float4* w4 = (const float4*)ln_w;
        const float4* b4 = (const float4*)ln_b;
        const float4* s4 = (const float4*)sel_w;

        float s = 0.f, ss = 0.f, d3 = 0.f, c1 = 0.f, c2 = 0.f;
        #pragma unroll
        for (int it = 0; it < 6; it++) {
            int c = lane + it * 32;
            float4 v = xr[c], w = w4[c], bb = b4[c], sw = s4[c];
            s  += v.x + v.y + v.z + v.w;
            ss += v.x*v.x + v.y*v.y + v.z*v.z + v.w*v.w;
            float wsx = w.x*sw.x, wsy = w.y*sw.y, wsz = w.z*sw.z, wsw = w.w*sw.w;
            d3 += v.x*wsx + v.y*wsy + v.z*wsz + v.w*wsw;
            c1 += wsx + wsy + wsz + wsw;
            c2 += bb.x*sw.x + bb.y*sw.y + bb.z*sw.z + bb.w*sw.w;
        }
        #pragma unroll
        for (int o = 16; o; o >>= 1) {
            s  += __shfl_xor_sync(0xffffffffu, s,  o);
            ss += __shfl_xor_sync(0xffffffffu, ss, o);
            d3 += __shfl_xor_sync(0xffffffffu, d3, o);
            c1 += __shfl_xor_sync(0xffffffffu, c1, o);
            c2 += __shfl_xor_sync(0xffffffffu, c2, o);
        }
        if (lane == 0) {
            float mu  = s * (1.f / C_);
            float var = ss * (1.f / C_) - mu * mu;
            float inv = rsqrtf(var + 1e-5f);
            float z = mscale[0] * (inv * (d3 - mu * c1) + c2) + sel_b[0];
            float sel = 1.f / (1.f + __expf(-z));
            g_gate[row] = 0.5f + 0.5f * sel;
        }
    }
}

// ============================================================
// tensor-core GEMM: 128xTN x32, 8 warps, cp.async 2-stage, ldmatrix
//   MODE 0: TN=128 : g_xh @ g_wa -> g_qkv (+bias, q scaled)
//   MODE 1: TN=64  : g_ah @ g_wp -> fp32 out + bias
// ============================================================
template <int MODE>
__global__ __launch_bounds__(256) void gemm_tc(const float* __restrict__ bias,
                                               float* __restrict__ out) {
    constexpr int TN = (MODE == 0) ? 128 : 64;
    constexpr int MI = (MODE == 0) ? 4 : 2;

    __shared__ __half As[2][128][40];
    __shared__ __half Bs[2][TN][40];

    const __half* A  = (MODE == 0) ? g_xh : g_ah;
    const __half* Bt = (MODE == 0) ? g_wa : g_wp;
    const int N = (MODE == 0) ? NC3_ : C_;
    const int K = C_;

    int tid  = threadIdx.x;
    int lane = tid & 31, ww = tid >> 5;
    int g = lane >> 2, t4 = lane & 3;
    int wm, wn;
    if (MODE == 0) { wm = (ww & 1) * 64; wn = (ww >> 1) * 32; }
    else           { wm = (ww & 3) * 32; wn = (ww >> 2) * 32; }
    int m0 = blockIdx.y * 128, n0 = blockIdx.x * TN;

    uint32_t asb = sm_u32(&As[0][0][0]);
    uint32_t bsb = sm_u32(&Bs[0][0][0]);
    const uint32_t STGA = 128 * 40 * 2;
    const uint32_t STGB = TN  * 40 * 2;

    int lr = lane & 7, sel = lane >> 3;
    int rowA = (sel & 1) * 8 + lr, colA = (sel >> 1) * 8;
    int rowB = (sel >> 1) * 8 + lr, colB = (sel & 1) * 8;

    int lrow = tid >> 2, lcol = (tid & 3) * 8;

    float acc[MI][4][4];
    #pragma unroll
    for (int mi = 0; mi < MI; mi++)
        #pragma unroll
        for (int ni = 0; ni < 4; ni++)
            #pragma unroll
            for (int e = 0; e < 4; e++) acc[mi][ni][e] = 0.f;

    auto load_stage = [&](int stage, int k0) {
        #pragma unroll
        for (int r = 0; r < 2; r++) {
            int row = lrow + r * 64;
            CP_A16(asb + stage * STGA + row * 80 + lcol * 2,
                   &A [(size_t)(m0 + row) * K + k0 + lcol]);
        }
        #pragma unroll
        for (int r = 0; r < TN / 64; r++) {
            int row = lrow + r * 64;
            CP_A16(bsb + stage * STGB + row * 80 + lcol * 2,
                   &Bt[(size_t)(n0 + row) * K + k0 + lcol]);
        }
    };

    load_stage(0, 0);  CP_COMMIT();
    load_stage(1, 32); CP_COMMIT();

    for (int k0 = 0, it = 0; k0 < K; k0 += 32, it++) {
        int stage = it & 1;
        CP_WAIT1();
        __syncthreads();

        #pragma unroll
        for (int kc = 0; kc < 2; kc++) {
            uint32_t af[MI][4];
            #pragma unroll
            for (int mi = 0; mi < MI; mi++)
                ldmx4(af[mi], asb + stage*STGA + (wm + mi*16 + rowA)*80 + (kc*16 + colA)*2);
            uint32_t bf0[4], bf1[4];
            ldmx4(bf0, bsb + stage*STGB + (wn +      rowB)*80 + (kc*16 + colB)*2);
            ldmx4(bf1, bsb + stage*STGB + (wn + 16 + rowB)*80 + (kc*16 + colB)*2);
            #pragma unroll
            for (int mi = 0; mi < MI; mi++) {
                mma16816(acc[mi][0], af[mi], bf0[0], bf0[1]);
                mma16816(acc[mi][1], af[mi], bf0[2], bf0[3]);
                mma16816(acc[mi][2], af[mi], bf1[0], bf1[1]);
                mma16816(acc[mi][3], af[mi], bf1[2], bf1[3]);
            }
        }
        __syncthreads();
        if (k0 + 64 < K) load_stage(stage, k0 + 64);
        CP_COMMIT();
    }

    // epilogue (coalesced in both modes)
    #pragma unroll
    for (int mi = 0; mi < MI; mi++) {
        #pragma unroll
        for (int ni = 0; ni < 4; ni++) {
            int n = n0 + wn + ni*8 + t4*2;
            float bv0 = bias[n], bv1 = bias[n+1];
            #pragma unroll
            for (int hh = 0; hh < 2; hh++) {
                int m = m0 + wm + mi*16 + g + hh*8;
                float v0 = acc[mi][ni][hh*2+0] + bv0;
                float v1 = acc[mi][ni][hh*2+1] + bv1;
                if (MODE == 0) {
                    float sc2 = (n < C_) ? QSCALE_ : 1.f;
                    *(__half2*)&g_qkv[(size_t)m * NC3_ + n] =
                        __floats2half2_rn(v0 * sc2, v1 * sc2);
                } else {
                    float2 v = make_float2(v0, v1);
                    *(float2*)&out[(size_t)m * C_ + n] = v;
                }
            }
        }
    }
}

// ============================================================
// tensor-core dual-softmax flash attention (exp2, no max)
//   128-key tiles (two 64-key subtiles per barrier), 3-stage
//   cp.async pipeline, ONE barrier per 128 keys, literal stages
//   grid (16, B*H), 256 threads; 128 q-rows/block, 16 rows/warp
// ============================================================
__global__ __launch_bounds__(256) void attn_tc(const float* __restrict__ lw_p,
                                               const float* __restrict__ gw_p) {
    __shared__ __half Qs[128][72];
    __shared__ __half Ks[3][128][72];
    __shared__ __half Vs[3][128][72];
    __shared__ float gsm[3][128];

    int bh = blockIdx.y;
    int b = bh / H_, h = bh % H_;
    int tid = threadIdx.x, lane = tid & 31, w = tid >> 5;
    int g = lane >> 2, t4 = lane & 3;
    int tix = gridDim.x - 1 - blockIdx.x;   // longest blocks first
    int i0 = tix * 128;
    int r0 = i0 + w * 16;
    int ia = r0 + g, ib = r0 + g + 8;
    int iwmax = r0 + 15;

    uint32_t qsb = sm_u32(&Qs[0][0]);
    uint32_t ksb = sm_u32(&Ks[0][0][0]);
    uint32_t vsb = sm_u32(&Vs[0][0][0]);
    const uint32_t STG = 128 * 72 * 2;   // bytes per stage

    int lr = lane & 7, sel = lane >> 3;
    int rowA = (sel & 1) * 8 + lr, colA = (sel >> 1) * 8;   // A-frag (Q)
    int rowB = (sel >> 1) * 8 + lr, colB = (sel & 1) * 8;   // B-frag (K)
    int rowV = (sel & 1) * 8 + lr, colV = (sel >> 1) * 8;   // B-frag via trans (V)

    const __half* qkvb = g_qkv + (size_t)b * T_ * NC3_;
    const __half* kcol = qkvb + C_     + h * 64;
    const __half* vcol = qkvb + 2 * C_ + h * 64;
    // 2 threads/row over 128 rows; each thread copies 4x16B per array
    int lrow = tid >> 1, lcol8 = (tid & 1) * 32;

    auto load_tile = [&](int stage, int j0) {
        const __half* ksrc = &kcol[(size_t)(j0 + lrow) * NC3_ + lcol8];
        const __half* vsrc = &vcol[(size_t)(j0 + lrow) * NC3_ + lcol8];
        uint32_t kdst = ksb + stage*STG + lrow*144 + lcol8*2;
        uint32_t vdst = vsb + stage*STG + lrow*144 + lcol8*2;
        #pragma unroll
        for (int c = 0; c < 4; c++) {
            CP_A16(kdst + c*16, ksrc + c*8);
            CP_A16(vdst + c*16, vsrc + c*8);
        }
        if (tid < 32)
            CP_A16(sm_u32(&gsm[stage][tid*4]), &g_gate[b*T_ + j0 + tid*4]);
    };

    // Q tile (plain loads, once; q already pre-scaled by gemm0)
    const __half* qcol = qkvb + h * 64;
    #pragma unroll
    for (int r = 0; r < 4; r++) {
        int li = tid + r * 256;
        int row = li >> 3, c8 = li & 7;
        *(uint4*)&Qs[row][c8*8] = *(const uint4*)&qcol[(size_t)(i0 + row) * NC3_ + c8*8];
    }
    int n128 = tix + 1;   // 128-key tiles needed
    load_tile(0, 0);   CP_COMMIT();
    load_tile(1, 128); CP_COMMIT();
    __syncthreads();

    uint32_t qa[4][4];
    #pragma unroll
    for (int kc = 0; kc < 4; kc++)
        ldmx4(qa[kc], qsb + (w*16 + rowA)*144 + (kc*16 + colA)*2);

    float og[8][4], ol[8][4];
    #pragma unroll
    for (int nt = 0; nt < 8; nt++)
        #pragma unroll
        for (int e = 0; e < 4; e++) { og[nt][e] = 0.f; ol[nt][e] = 0.f; }
    float s_g0 = 0.f, s_g1 = 0.f, s_l0 = 0.f, s_l1 = 0.f;
    const float NEG = -3e38f;

// ---- one 64-key subtile; SC and SUB are LITERALS ----
#define ATTN_SUB(SC, SUB)                                                     \
    {                                                                         \
        int j0 = jt * 128 + (SUB) * 64;                                       \
        if (j0 <= iwmax) {                                                    \
            float s[8][4];                                                    \
            _Pragma("unroll")                                                 \
            for (int nt = 0; nt < 8; nt++)                                    \
                s[nt][0] = s[nt][1] = s[nt][2] = s[nt][3] = 0.f;              \
            _Pragma("unroll")                                                 \
            for (int kc = 0; kc < 4; kc++) {                                  \
                uint32_t kb[4][4];                                            \
                _Pragma("unroll")                                             \
                for (int ntb = 0; ntb < 4; ntb++)                             \
                    ldmx4(kb[ntb], ksb + (SC)*STG + ((SUB)*64 + ntb*16 + rowB)*144 + (kc*16 + colB)*2); \
                _Pragma("unroll")                                             \
                for (int nt = 0; nt < 8; nt++)                                \
                    mma16816(s[nt], qa[kc], kb[nt>>1][(nt&1)*2], kb[nt>>1][(nt&1)*2+1]); \
            }                                                                 \
            if (j0 + 63 > r0) {                                               \
                _Pragma("unroll")                                             \
                for (int nt = 0; nt < 8; nt++) {                              \
                    int j = j0 + nt*8 + t4*2;                                 \
                    if (j   > ia) s[nt][0] = NEG;                             \
                    if (j+1 > ia) s[nt][1] = NEG;                             \
                    if (j   > ib) s[nt][2] = NEG;                             \
                    if (j+1 > ib) s[nt][3] = NEG;                             \
                }                                                             \
            }                                                                 \
            uint32_t vb[4][4][4];                                             \
            _Pragma("unroll")                                                 \
            for (int kc = 0; kc < 4; kc++)                                    \
                _Pragma("unroll")                                             \
                for (int ntb = 0; ntb < 4; ntb++)                             \
                    ldmx4t(vb[kc][ntb], vsb + (SC)*STG + ((SUB)*64 + kc*16 + rowV)*144 + (ntb*16 + colV)*2); \
            float p[8][4];                                                    \
            if (j0 + 63 >= r0 - WIN_) {                                       \
                float ps0 = 0.f, ps1 = 0.f;                                   \
                if (j0 < iwmax - WIN_) {                                      \
                    _Pragma("unroll")                                         \
                    for (int nt = 0; nt < 8; nt++) {                          \
                        int j = j0 + nt*8 + t4*2;                             \
                        p[nt][0] = (j   >= ia - WIN_) ? ex2(s[nt][0]) : 0.f;  \
                        p[nt][1] = (j+1 >= ia - WIN_) ? ex2(s[nt][1]) : 0.f;  \
                        p[nt][2] = (j   >= ib - WIN_) ? ex2(s[nt][2]) : 0.f;  \
                        p[nt][3] = (j+1 >= ib - WIN_) ? ex2(s[nt][3]) : 0.f;  \
                        ps0 += p[nt][0] + p[nt][1];                           \
                        ps1 += p[nt][2] + p[nt][3];                           \
                    }                                                         \
                } else {                                                      \
                    _Pragma("unroll")                                         \
                    for (int nt = 0; nt < 8; nt++) {                          \
                        p[nt][0] = ex2(s[nt][0]);                             \
                        p[nt][1] = ex2(s[nt][1]);                             \
                        p[nt][2] = ex2(s[nt][2]);                             \
                        p[nt][3] = ex2(s[nt][3]);                             \
                        ps0 += p[nt][0] + p[nt][1];                           \
                        ps1 += p[nt][2] + p[nt][3];                           \
                    }                                                         \
                }                                                             \
                s_l0 += ps0;                                                  \
                s_l1 += ps1;                                                  \
                _Pragma("unroll")                                             \
                for (int kc = 0; kc < 4; kc++) {                              \
                    uint32_t af[4];                                           \
                    af[0] = pack2(p[2*kc  ][0], p[2*kc  ][1]);                \
                    af[1] = pack2(p[2*kc  ][2], p[2*kc  ][3]);                \
                    af[2] = pack2(p[2*kc+1][0], p[2*kc+1][1]);                \
                    af[3] = pack2(p[2*kc+1][2], p[2*kc+1][3]);                \
                    _Pragma("unroll")                                         \
                    for (int nt = 0; nt < 8; nt++)                            \
                        mma16816(ol[nt], af, vb[kc][nt>>1][(nt&1)*2], vb[kc][nt>>1][(nt&1)*2+1]); \
                }                                                             \
            }                                                                 \
            {                                                                 \
                float ps0 = 0.f, ps1 = 0.f;                                   \
                _Pragma("unroll")                                             \
                for (int nt = 0; nt < 8; nt++) {                              \
                    float ga = gsm[(SC)][(SUB)*64 + nt*8 + t4*2];             \
                    float gb = gsm[(SC)][(SUB)*64 + nt*8 + t4*2 + 1];         \
                    s[nt][0] = ex2(s[nt][0] * ga);                            \
                    s[nt][1] = ex2(s[nt][1] * gb);                            \
                    s[nt][2] = ex2(s[nt][2] * ga);                            \
                    s[nt][3] = ex2(s[nt][3] * gb);                            \
                    ps0 += s[nt][0] + s[nt][1];                               \
                    ps1 += s[nt][2] + s[nt][3];                               \
                }                                                             \
                s_g0 += ps0;                                                  \
                s_g1 += ps1;                                                  \
                _Pragma("unroll")                                             \
                for (int kc = 0; kc < 4; kc++) {                              \
                    uint32_t af[4];                                           \
                    af[0] = pack2(s[2*kc  ][0], s[2*kc  ][1]);                \
                    af[1] = pack2(s[2*kc  ][2], s[2*kc  ][3]);                \
                    af[2] = pack2(s[2*kc+1][0], s[2*kc+1][1]);                \
                    af[3] = pack2(s[2*kc+1][2], s[2*kc+1][3]);                \
                    _Pragma("unroll")                                         \
                    for (int nt = 0; nt < 8; nt++)                            \
                        mma16816(og[nt], af, vb[kc][nt>>1][(nt&1)*2], vb[kc][nt>>1][(nt&1)*2+1]); \
                }                                                             \
            }                                                                 \
        }                                                                     \
    }

#define ATTN_TILE(SC, SL)                                                     \
    {                                                                         \
        CP_WAIT1();                                                           \
        __syncthreads();                                                      \
        if (jt + 2 < n128) load_tile((SL), (jt + 2) * 128);                   \
        CP_COMMIT();                                                          \
        ATTN_SUB(SC, 0)                                                       \
        ATTN_SUB(SC, 1)                                                       \
    }

    int jt = 0;
    while (true) {
        ATTN_TILE(0, 2); if (++jt == n128) break;
        ATTN_TILE(1, 0); if (++jt == n128) break;
        ATTN_TILE(2, 1); if (++jt == n128) break;
    }
#undef ATTN_TILE
#undef ATTN_SUB

    // ---- deferred quad-reduction of softmax sums ----
    #pragma unroll
    for (int o = 1; o <= 2; o <<= 1) {
        s_l0 += __shfl_xor_sync(0xffffffffu, s_l0, o);
        s_l1 += __shfl_xor_sync(0xffffffffu, s_l1, o);
        s_g0 += __shfl_xor_sync(0xffffffffu, s_g0, o);
        s_g1 += __shfl_xor_sync(0xffffffffu, s_g1, o);
    }

    // ---- epilogue: combine branches, write fp16 [b,t,C] ----
    float wl = 1.f / (1.f + __expf(-lw_p[0]));
    float wg = 1.f / (1.f + __expf(-gw_p[0]));
    float wi = 1.f / (wl + wg);
    wl *= wi; wg *= wi;
    float il0 = wl / s_l0, il1 = wl / s_l1;
    float ig0 = wg / s_g0, ig1 = wg / s_g1;

    #pragma unroll
    for (int nt = 0; nt < 8; nt++) {
        int col = h * 64 + nt*8 + t4*2;
        float o0 = ol[nt][0]*il0 + og[nt][0]*ig0;
        float o1 = ol[nt][1]*il0 + og[nt][1]*ig0;
        *(__half2*)&g_ah[((size_t)b*T_ + ia)*C_ + col] = __floats2half2_rn(o0, o1);
        float o2 = ol[nt][2]*il1 + og[nt][2]*ig1;
        float o3 = ol[nt][3]*il1 + og[nt][3]*ig1;
        *(__half2*)&g_ah[((size_t)b*T_ + ib)*C_ + col] = __floats2half2_rn(o2, o3);
    }
}

// ============================================================
// launch
// ============================================================
extern "C" void kernel_launch(void* const* d_in, const int* in_sizes, int n_in,
                              void* d_out, int out_size) {
    const float* x        = (const float*)d_in[0];
    const float* mamba    = (const float*)d_in[1];
    const float* c_attn_w = (const float*)d_in[2];
    const float* c_attn_b = (const float*)d_in[3];
    const float* c_proj_w = (const float*)d_in[4];
    const float* c_proj_b = (const float*)d_in[5];
    const float* ln_w     = (const float*)d_in[6];
    const float* ln_b     = (const float*)d_in[7];
    const float* mscale   = (const float*)d_in[8];
    const float* sel_w    = (const float*)d_in[9];
    const float* sel_b    = (const float*)d_in[10];
    const float* lw       = (const float*)d_in[11];
    const float* gw       = (const float*)d_in[12];
    float* out = (float*)d_out;

    prep_a_kernel<<<PREP_X_ + PREP_WA_, 256>>>((const float4*)x, c_attn_w);
    prep_b_kernel<<<PREP_WP_ + PREP_SEL_, 256>>>(c_proj_w, mamba,
                                                 ln_w, ln_b, mscale, sel_w, sel_b);
    gemm_tc<0><<<dim3(18, 32), 256>>>(c_attn_b, nullptr);
    attn_tc<<<dim3(16, B_*H_), 256>>>(lw, gw);
    gemm_tc<1><<<dim3(12, 32), 256>>>(c_proj_b, out);
}

// round 17
// speedup vs baseline: 1.0444x; 1.0444x over previous
#include <cuda_runtime.h>
#include <cuda_fp16.h>
#include <stdint.h>

#define B_ 2
#define T_ 2048
#define C_ 768
#define H_ 12
#define D_ 64
#define WIN_ 256
#define NC3_ (3*C_)
#define QSCALE_ 0.18033688011112042f   // 0.125 * log2(e)

// -------- scratch (allocation-free: __device__ globals) --------
__device__ __align__(16) __half g_xh[B_*T_*C_];
__device__ __align__(16) __half g_wa[3*C_*C_];    // c_attn_w transposed: [n][k]
__device__ __align__(16) __half g_wp[C_*C_];      // c_proj_w transposed: [n][k]
__device__ __align__(16) __half g_qkv[B_*T_*NC3_]; // [b,t,3C]; q part pre-scaled
__device__ __align__(16) __half g_ah[B_*T_*C_];   // attention out, fp16
__device__ float g_gate[B_*T_];

// ============================================================
// helpers
// ============================================================
__device__ __forceinline__ void mma16816(float* d, const uint32_t* a,
                                         uint32_t b0, uint32_t b1) {
    asm volatile(
        "mma.sync.aligned.m16n8k16.row.col.f32.f16.f16.f32 "
        "{%0,%1,%2,%3}, {%4,%5,%6,%7}, {%8,%9}, {%0,%1,%2,%3};"
        : "+f"(d[0]), "+f"(d[1]), "+f"(d[2]), "+f"(d[3])
        : "r"(a[0]), "r"(a[1]), "r"(a[2]), "r"(a[3]), "r"(b0), "r"(b1));
}

__device__ __forceinline__ void ldmx4(uint32_t* r, uint32_t addr) {
    asm volatile("ldmatrix.sync.aligned.m8n8.x4.shared.b16 {%0,%1,%2,%3}, [%4];"
                 : "=r"(r[0]), "=r"(r[1]), "=r"(r[2]), "=r"(r[3]) : "r"(addr));
}
__device__ __forceinline__ void ldmx4t(uint32_t* r, uint32_t addr) {
    asm volatile("ldmatrix.sync.aligned.m8n8.x4.trans.shared.b16 {%0,%1,%2,%3}, [%4];"
                 : "=r"(r[0]), "=r"(r[1]), "=r"(r[2]), "=r"(r[3]) : "r"(addr));
}

__device__ __forceinline__ uint32_t pack2(float a, float b) {
    __half2 h = __floats2half2_rn(a, b);
    return *(uint32_t*)&h;
}

__device__ __forceinline__ float ex2(float x) {
    float y;
    asm("ex2.approx.ftz.f32 %0, %1;" : "=f"(y) : "f"(x));
    return y;
}

__device__ __forceinline__ uint32_t sm_u32(const void* p) {
    return (uint32_t)__cvta_generic_to_shared(p);
}

#define CP_A16(dst, src) \
    asm volatile("cp.async.cg.shared.global [%0], [%1], 16;" :: "r"(dst), "l"(src))
#define CP_COMMIT()  asm volatile("cp.async.commit_group;")
#define CP_WAIT1()   asm volatile("cp.async.wait_group 1;")

// ============================================================
// merged prep kernel: conv_x | wT(c_attn) | wT(c_proj) | sel/gate
// ============================================================
#define PREP_X_   3072
#define PREP_WA_  1728
#define PREP_WP_  576
#define PREP_SEL_ 512

__global__ __launch_bounds__(256) void prep_kernel(
        const float4* __restrict__ x4,
        const float*  __restrict__ c_attn_w,
        const float*  __restrict__ c_proj_w,
        const float*  __restrict__ mamba,
        const float*  __restrict__ ln_w,
        const float*  __restrict__ ln_b,
        const float*  __restrict__ mscale,
        const float*  __restrict__ sel_w,
        const float*  __restrict__ sel_b) {
    __shared__ float tile[32][33];
    int bid = blockIdx.x;
    int tid = threadIdx.x;

    if (bid < PREP_X_) {
        int i = bid * 256 + tid;
        float4 f = x4[i];
        uint2 o;
        o.x = pack2(f.x, f.y);
        o.y = pack2(f.z, f.w);
        *(uint2*)&g_xh[(size_t)i * 4] = o;
        return;
    }
    bid -= PREP_X_;
    if (bid < PREP_WA_ + PREP_WP_) {
        int N; __half* out; int bx, by;
        const float* in;
        if (bid < PREP_WA_) { N = NC3_; out = g_wa; in = c_attn_w; bx = bid % 72; by = bid / 72; }
        else { bid -= PREP_WA_; N = C_; out = g_wp; in = c_proj_w; bx = bid % 24; by = bid / 24; }
        int bn = bx * 32, bk = by * 32;
        int tx = tid & 31, ty = tid >> 5;
        #pragma unroll
        for (int r = 0; r < 4; r++) {
            int k = bk + ty + r * 8;
            tile[ty + r * 8][tx] = in[(size_t)k * N + bn + tx];
        }
        __syncthreads();
        #pragma unroll
        for (int r = 0; r < 4; r++) {
            int n = bn + ty + r * 8;
            out[(size_t)n * C_ + bk + tx] = __float2half(tile[tx][ty + r * 8]);
        }
        return;
    }
    bid -= PREP_WA_ + PREP_WP_;
    {
        int row  = bid * 8 + (tid >> 5);
        int lane = tid & 31;
        const float4* xr = (const float4*)(mamba + (size_t)row * C_);
        const float4* w4 = (const float4*)ln_w;
        const float4* b4 = (const float4*)ln_b;
        const float4* s4 = (const float4*)sel_w;

        float s = 0.f, ss = 0.f, d3 = 0.f, c1 = 0.f, c2 = 0.f;
        #pragma unroll
        for (int it = 0; it < 6; it++) {
            int c = lane + it * 32;
            float4 v = xr[c], w = w4[c], bb = b4[c], sw = s4[c];
            s  += v.x + v.y + v.z + v.w;
            ss += v.x*v.x + v.y*v.y + v.z*v.z + v.w*v.w;
            float wsx = w.x*sw.x, wsy = w.y*sw.y, wsz = w.z*sw.z, wsw = w.w*sw.w;
            d3 += v.x*wsx + v.y*wsy + v.z*wsz + v.w*wsw;
            c1 += wsx + wsy + wsz + wsw;
            c2 += bb.x*sw.x + bb.y*sw.y + bb.z*sw.z + bb.w*sw.w;
        }
        #pragma unroll
        for (int o = 16; o; o >>= 1) {
            s  += __shfl_xor_sync(0xffffffffu, s,  o);
            ss += __shfl_xor_sync(0xffffffffu, ss, o);
            d3 += __shfl_xor_sync(0xffffffffu, d3, o);
            c1 += __shfl_xor_sync(0xffffffffu, c1, o);
            c2 += __shfl_xor_sync(0xffffffffu, c2, o);
        }
        if (lane == 0) {
            float mu  = s * (1.f / C_);
            float var = ss * (1.f / C_) - mu * mu;
            float inv = rsqrtf(var + 1e-5f);
            float z = mscale[0] * (inv * (d3 - mu * c1) + c2) + sel_b[0];
            float sel = 1.f / (1.f + __expf(-z));
            g_gate[row] = 0.5f + 0.5f * sel;
        }
    }
}

// ============================================================
// tensor-core GEMM: 128xTN x32, 8 warps, cp.async 2-stage, ldmatrix
//   MODE 0: TN=128 : g_xh @ g_wa -> g_qkv (+bias, q scaled)
//   MODE 1: TN=64  : g_ah @ g_wp -> fp32 out + bias
// ============================================================
template <int MODE>
__global__ __launch_bounds__(256) void gemm_tc(const float* __restrict__ bias,
                                               float* __restrict__ out) {
    constexpr int TN = (MODE == 0) ? 128 : 64;
    constexpr int MI = (MODE == 0) ? 4 : 2;

    __shared__ __half As[2][128][40];
    __shared__ __half Bs[2][TN][40];

    const __half* A  = (MODE == 0) ? g_xh : g_ah;
    const __half* Bt = (MODE == 0) ? g_wa : g_wp;
    const int N = (MODE == 0) ? NC3_ : C_;
    const int K = C_;

    int tid  = threadIdx.x;
    int lane = tid & 31, ww = tid >> 5;
    int g = lane >> 2, t4 = lane & 3;
    int wm, wn;
    if (MODE == 0) { wm = (ww & 1) * 64; wn = (ww >> 1) * 32; }
    else           { wm = (ww & 3) * 32; wn = (ww >> 2) * 32; }
    int m0 = blockIdx.y * 128, n0 = blockIdx.x * TN;

    uint32_t asb = sm_u32(&As[0][0][0]);
    uint32_t bsb = sm_u32(&Bs[0][0][0]);
    const uint32_t STGA = 128 * 40 * 2;
    const uint32_t STGB = TN  * 40 * 2;

    int lr = lane & 7, sel = lane >> 3;
    int rowA = (sel & 1) * 8 + lr, colA = (sel >> 1) * 8;
    int rowB = (sel >> 1) * 8 + lr, colB = (sel & 1) * 8;

    int lrow = tid >> 2, lcol = (tid & 3) * 8;

    float acc[MI][4][4];
    #pragma unroll
    for (int mi = 0; mi < MI; mi++)
        #pragma unroll
        for (int ni = 0; ni < 4; ni++)
            #pragma unroll
            for (int e = 0; e < 4; e++) acc[mi][ni][e] = 0.f;

    auto load_stage = [&](int stage, int k0) {
        #pragma unroll
        for (int r = 0; r < 2; r++) {
            int row = lrow + r * 64;
            CP_A16(asb + stage * STGA + row * 80 + lcol * 2,
                   &A [(size_t)(m0 + row) * K + k0 + lcol]);
        }
        #pragma unroll
        for (int r = 0; r < TN / 64; r++) {
            int row = lrow + r * 64;
            CP_A16(bsb + stage * STGB + row * 80 + lcol * 2,
                   &Bt[(size_t)(n0 + row) * K + k0 + lcol]);
        }
    };

    load_stage(0, 0);  CP_COMMIT();
    load_stage(1, 32); CP_COMMIT();

    for (int k0 = 0, it = 0; k0 < K; k0 += 32, it++) {
        int stage = it & 1;
        CP_WAIT1();
        __syncthreads();

        #pragma unroll
        for (int kc = 0; kc < 2; kc++) {
            uint32_t af[MI][4];
            #pragma unroll
            for (int mi = 0; mi < MI; mi++)
                ldmx4(af[mi], asb + stage*STGA + (wm + mi*16 + rowA)*80 + (kc*16 + colA)*2);
            uint32_t bf0[4], bf1[4];
            ldmx4(bf0, bsb + stage*STGB + (wn +      rowB)*80 + (kc*16 + colB)*2);
            ldmx4(bf1, bsb + stage*STGB + (wn + 16 + rowB)*80 + (kc*16 + colB)*2);
            #pragma unroll
            for (int mi = 0; mi < MI; mi++) {
                mma16816(acc[mi][0], af[mi], bf0[0], bf0[1]);
                mma16816(acc[mi][1], af[mi], bf0[2], bf0[3]);
                mma16816(acc[mi][2], af[mi], bf1[0], bf1[1]);
                mma16816(acc[mi][3], af[mi], bf1[2], bf1[3]);
            }
        }
        __syncthreads();
        if (k0 + 64 < K) load_stage(stage, k0 + 64);
        CP_COMMIT();
    }

    // epilogue (coalesced in both modes)
    #pragma unroll
    for (int mi = 0; mi < MI; mi++) {
        #pragma unroll
        for (int ni = 0; ni < 4; ni++) {
            int n = n0 + wn + ni*8 + t4*2;
            float bv0 = bias[n], bv1 = bias[n+1];
            #pragma unroll
            for (int hh = 0; hh < 2; hh++) {
                int m = m0 + wm + mi*16 + g + hh*8;
                float v0 = acc[mi][ni][hh*2+0] + bv0;
                float v1 = acc[mi][ni][hh*2+1] + bv1;
                if (MODE == 0) {
                    float sc2 = (n < C_) ? QSCALE_ : 1.f;
                    *(__half2*)&g_qkv[(size_t)m * NC3_ + n] =
                        __floats2half2_rn(v0 * sc2, v1 * sc2);
                } else {
                    float2 v = make_float2(v0, v1);
                    *(float2*)&out[(size_t)m * C_ + n] = v;
                }
            }
        }
    }
}

// ============================================================
// tensor-core dual-softmax flash attention (exp2, no max)
//   3-stage cp.async pipeline, ONE barrier/tile, stages as
//   compile-time literals (loop unrolled x3 via macro)
//   grid (16, B*H), 256 threads; 128 q-rows/block, 16 rows/warp
//   (R14 configuration — verified 89.9us)
// ============================================================
__global__ __launch_bounds__(256) void attn_tc(const float* __restrict__ lw_p,
                                               const float* __restrict__ gw_p) {
    __shared__ __half Qs[128][72];
    __shared__ __half Ks[3][64][72];
    __shared__ __half Vs[3][64][72];
    __shared__ float gsm[3][64];

    int bh = blockIdx.y;
    int b = bh / H_, h = bh % H_;
    int tid = threadIdx.x, lane = tid & 31, w = tid >> 5;
    int g = lane >> 2, t4 = lane & 3;
    int tix = gridDim.x - 1 - blockIdx.x;   // longest blocks first
    int i0 = tix * 128;
    int r0 = i0 + w * 16;
    int ia = r0 + g, ib = r0 + g + 8;
    int iwmax = r0 + 15;

    uint32_t qsb = sm_u32(&Qs[0][0]);
    uint32_t ksb = sm_u32(&Ks[0][0][0]);
    uint32_t vsb = sm_u32(&Vs[0][0][0]);
    const uint32_t STG = 64 * 72 * 2;

    int lr = lane & 7, sel = lane >> 3;
    int rowA = (sel & 1) * 8 + lr, colA = (sel >> 1) * 8;   // A-frag (Q)
    int rowB = (sel >> 1) * 8 + lr, colB = (sel & 1) * 8;   // B-frag (K)
    int rowV = (sel & 1) * 8 + lr, colV = (sel >> 1) * 8;   // B-frag via trans (V)

    const __half* qkvb = g_qkv + (size_t)b * T_ * NC3_;
    const __half* kcol = qkvb + C_     + h * 64;
    const __half* vcol = qkvb + 2 * C_ + h * 64;
    int lrow = tid >> 2, lcol8 = (tid & 3) * 16;

    auto load_tile = [&](int stage, int j0) {
        const __half* ksrc = &kcol[(size_t)(j0 + lrow) * NC3_ + lcol8];
        const __half* vsrc = &vcol[(size_t)(j0 + lrow) * NC3_ + lcol8];
        uint32_t kdst = ksb + stage*STG + lrow*144 + lcol8*2;
        uint32_t vdst = vsb + stage*STG + lrow*144 + lcol8*2;
        CP_A16(kdst,      ksrc);
        CP_A16(kdst + 16, ksrc + 8);
        CP_A16(vdst,      vsrc);
        CP_A16(vdst + 16, vsrc + 8);
        if (tid < 16)
            CP_A16(sm_u32(&gsm[stage][tid*4]), &g_gate[b*T_ + j0 + tid*4]);
    };

    // Q tile (plain loads, once; q already pre-scaled by gemm0)
    const __half* qcol = qkvb + h * 64;
    #pragma unroll
    for (int r = 0; r < 4; r++) {
        int li = tid + r * 256;
        int row = li >> 3, c8 = li & 7;
        *(uint4*)&Qs[row][c8*8] = *(const uint4*)&qcol[(size_t)(i0 + row) * NC3_ + c8*8];
    }
    int ntiles = 2 * tix + 2;
    load_tile(0, 0);  CP_COMMIT();
    load_tile(1, 64); CP_COMMIT();
    __syncthreads();

    uint32_t qa[4][4];
    #pragma unroll
    for (int kc = 0; kc < 4; kc++)
        ldmx4(qa[kc], qsb + (w*16 + rowA)*144 + (kc*16 + colA)*2);

    float og[8][4], ol[8][4];
    #pragma unroll
    for (int nt = 0; nt < 8; nt++)
        #pragma unroll
        for (int e = 0; e < 4; e++) { og[nt][e] = 0.f; ol[nt][e] = 0.f; }
    float s_g0 = 0.f, s_g1 = 0.f, s_l0 = 0.f, s_l1 = 0.f;
    const float NEG = -3e38f;

// ---- one tile iteration; SC/SL are LITERAL stage indices ----
#define ATTN_TILE(SC, SL)                                                     \
    {                                                                         \
        int j0 = jt * 64;                                                     \
        CP_WAIT1();                                                           \
        __syncthreads();                                                      \
        if (jt + 2 < ntiles) load_tile((SL), (jt + 2) * 64);                  \
        CP_COMMIT();                                                          \
        if (j0 <= iwmax) {                                                    \
            float s[8][4];                                                    \
            _Pragma("unroll")                                                 \
            for (int nt = 0; nt < 8; nt++)                                    \
                s[nt][0] = s[nt][1] = s[nt][2] = s[nt][3] = 0.f;              \
            _Pragma("unroll")                                                 \
            for (int kc = 0; kc < 4; kc++) {                                  \
                uint32_t kb[4][4];                                            \
                _Pragma("unroll")                                             \
                for (int ntb = 0; ntb < 4; ntb++)                             \
                    ldmx4(kb[ntb], ksb + (SC)*STG + (ntb*16 + rowB)*144 + (kc*16 + colB)*2); \
                _Pragma("unroll")                                             \
                for (int nt = 0; nt < 8; nt++)                                \
                    mma16816(s[nt], qa[kc], kb[nt>>1][(nt&1)*2], kb[nt>>1][(nt&1)*2+1]); \
            }                                                                 \
            if (j0 + 63 > r0) {                                               \
                _Pragma("unroll")                                             \
                for (int nt = 0; nt < 8; nt++) {                              \
                    int j = j0 + nt*8 + t4*2;                                 \
                    if (j   > ia) s[nt][0] = NEG;                             \
                    if (j+1 > ia) s[nt][1] = NEG;                             \
                    if (j   > ib) s[nt][2] = NEG;                             \
                    if (j+1 > ib) s[nt][3] = NEG;                             \
                }                                                             \
            }                                                                 \
            uint32_t vb[4][4][4];                                             \
            _Pragma("unroll")                                                 \
            for (int kc = 0; kc < 4; kc++)                                    \
                _Pragma("unroll")                                             \
                for (int ntb = 0; ntb < 4; ntb++)                             \
                    ldmx4t(vb[kc][ntb], vsb + (SC)*STG + (kc*16 + rowV)*144 + (ntb*16 + colV)*2); \
            float p[8][4];                                                    \
            if (j0 + 63 >= r0 - WIN_) {                                       \
                float ps0 = 0.f, ps1 = 0.f;                                   \
                if (j0 < iwmax - WIN_) {                                      \
                    _Pragma("unroll")                                         \
                    for (int nt = 0; nt < 8; nt++) {                          \
                        int j = j0 + nt*8 + t4*2;                             \
                        p[nt][0] = (j   >= ia - WIN_) ? ex2(s[nt][0]) : 0.f;  \
                        p[nt][1] = (j+1 >= ia - WIN_) ? ex2(s[nt][1]) : 0.f;  \
                        p[nt][2] = (j   >= ib - WIN_) ? ex2(s[nt][2]) : 0.f;  \
                        p[nt][3] = (j+1 >= ib - WIN_) ? ex2(s[nt][3]) : 0.f;  \
                        ps0 += p[nt][0] + p[nt][1];                           \
                        ps1 += p[nt][2] + p[nt][3];                           \
                    }                                                         \
                } else {                                                      \
                    _Pragma("unroll")                                         \
                    for (int nt = 0; nt < 8; nt++) {                          \
                        p[nt][0] = ex2(s[nt][0]);                             \
                        p[nt][1] = ex2(s[nt][1]);                             \
                        p[nt][2] = ex2(s[nt][2]);                             \
                        p[nt][3] = ex2(s[nt][3]);                             \
                        ps0 += p[nt][0] + p[nt][1];                           \
                        ps1 += p[nt][2] + p[nt][3];                           \
                    }                                                         \
                }                                                             \
                s_l0 += ps0;                                                  \
                s_l1 += ps1;                                                  \
                _Pragma("unroll")                                             \
                for (int kc = 0; kc < 4; kc++) {                              \
                    uint32_t af[4];                                           \
                    af[0] = pack2(p[2*kc  ][0], p[2*kc  ][1]);                \
                    af[1] = pack2(p[2*kc  ][2], p[2*kc  ][3]);                \
                    af[2] = pack2(p[2*kc+1][0], p[2*kc+1][1]);                \
                    af[3] = pack2(p[2*kc+1][2], p[2*kc+1][3]);                \
                    _Pragma("unroll")                                         \
                    for (int nt = 0; nt < 8; nt++)                            \
                        mma16816(ol[nt], af, vb[kc][nt>>1][(nt&1)*2], vb[kc][nt>>1][(nt&1)*2+1]); \
                }                                                             \
            }                                                                 \
            {                                                                 \
                float ps0 = 0.f, ps1 = 0.f;                                   \
                _Pragma("unroll")                                             \
                for (int nt = 0; nt < 8; nt++) {                              \
                    float ga = gsm[(SC)][nt*8 + t4*2];                        \
                    float gb = gsm[(SC)][nt*8 + t4*2 + 1];                    \
                    s[nt][0] = ex2(s[nt][0] * ga);                            \
                    s[nt][1] = ex2(s[nt][1] * gb);                            \
                    s[nt][2] = ex2(s[nt][2] * ga);                            \
                    s[nt][3] = ex2(s[nt][3] * gb);                            \
                    ps0 += s[nt][0] + s[nt][1];                               \
                    ps1 += s[nt][2] + s[nt][3];                               \
                }                                                             \
                s_g0 += ps0;                                                  \
                s_g1 += ps1;                                                  \
                _Pragma("unroll")                                             \
                for (int kc = 0; kc < 4; kc++) {                              \
                    uint32_t af[4];                                           \
                    af[0] = pack2(s[2*kc  ][0], s[2*kc  ][1]);                \
                    af[1] = pack2(s[2*kc  ][2], s[2*kc  ][3]);                \
                    af[2] = pack2(s[2*kc+1][0], s[2*kc+1][1]);                \
                    af[3] = pack2(s[2*kc+1][2], s[2*kc+1][3]);                \
                    _Pragma("unroll")                                         \
                    for (int nt = 0; nt < 8; nt++)                            \
                        mma16816(og[nt], af, vb[kc][nt>>1][(nt&1)*2], vb[kc][nt>>1][(nt&1)*2+1]); \
                }                                                             \
            }                                                                 \
        }                                                                     \
    }

    int jt = 0;
    while (true) {
        ATTN_TILE(0, 2); if (++jt == ntiles) break;
        ATTN_TILE(1, 0); if (++jt == ntiles) break;
        ATTN_TILE(2, 1); if (++jt == ntiles) break;
    }
#undef ATTN_TILE

    // ---- deferred quad-reduction of softmax sums ----
    #pragma unroll
    for (int o = 1; o <= 2; o <<= 1) {
        s_l0 += __shfl_xor_sync(0xffffffffu, s_l0, o);
        s_l1 += __shfl_xor_sync(0xffffffffu, s_l1, o);
        s_g0 += __shfl_xor_sync(0xffffffffu, s_g0, o);
        s_g1 += __shfl_xor_sync(0xffffffffu, s_g1, o);
    }

    // ---- epilogue: combine branches, write fp16 [b,t,C] ----
    float wl = 1.f / (1.f + __expf(-lw_p[0]));
    float wg = 1.f / (1.f + __expf(-gw_p[0]));
    float wi = 1.f / (wl + wg);
    wl *= wi; wg *= wi;
    float il0 = wl / s_l0, il1 = wl / s_l1;
    float ig0 = wg / s_g0, ig1 = wg / s_g1;

    #pragma unroll
    for (int nt = 0; nt < 8; nt++) {
        int col = h * 64 + nt*8 + t4*2;
        float o0 = ol[nt][0]*il0 + og[nt][0]*ig0;
        float o1 = ol[nt][1]*il0 + og[nt][1]*ig0;
        *(__half2*)&g_ah[((size_t)b*T_ + ia)*C_ + col] = __floats2half2_rn(o0, o1);
        float o2 = ol[nt][2]*il1 + og[nt][2]*ig1;
        float o3 = ol[nt][3]*il1 + og[nt][3]*ig1;
        *(__half2*)&g_ah[((size_t)b*T_ + ib)*C_ + col] = __floats2half2_rn(o2, o3);
    }
}

// ============================================================
// launch
// ============================================================
extern "C" void kernel_launch(void* const* d_in, const int* in_sizes, int n_in,
                              void* d_out, int out_size) {
    const float* x        = (const float*)d_in[0];
    const float* mamba    = (const float*)d_in[1];
    const float* c_attn_w = (const float*)d_in[2];
    const float* c_attn_b = (const float*)d_in[3];
    const float* c_proj_w = (const float*)d_in[4];
    const float* c_proj_b = (const float*)d_in[5];
    const float* ln_w     = (const float*)d_in[6];
    const float* ln_b     = (const float*)d_in[7];
    const float* mscale   = (const float*)d_in[8];
    const float* sel_w    = (const float*)d_in[9];
    const float* sel_b    = (const float*)d_in[10];
    const float* lw       = (const float*)d_in[11];
    const float* gw       = (const float*)d_in[12];
    float* out = (float*)d_out;

    prep_kernel<<<PREP_X_ + PREP_WA_ + PREP_WP_ + PREP_SEL_, 256>>>(
        (const float4*)x, c_attn_w, c_proj_w, mamba,
        ln_w, ln_b, mscale, sel_w, sel_b);
    gemm_tc<0><<<dim3(18, 32), 256>>>(c_attn_b, nullptr);
    attn_tc<<<dim3(16, B_*H_), 256>>>(lw, gw);
    gemm_tc<1><<<dim3(12, 32), 256>>>(c_proj_b, out);
}